// round 16
// baseline (speedup 1.0000x reference)
#include <cuda_runtime.h>
#include <cuda_fp16.h>
#include <math.h>
#include <stdint.h>

// GMM_64003602645506 — warp-independent fp16 mma.sync GEMM, barrier-free.
// R16: R15 fused kernel + two-phase tail splitting: phase A = one 32-sample
// unit per warp (dynamic), phase B = 16-sample half-units for the remainder.

#define D        32
#define K        64
#define NG       84
#define NKS      42
#define UNIT     32
#define TPB      512
#define NWARP    16
#define LOG_2PI  1.8378770664093453f

// smem layout (bytes)
#define SB_WORDS  (NKS * 4 * 32 * 4)          // 21504 uint32 (86016 B)
#define SB_OFF    0
#define XBUF_W    (UNIT * 20)                 // 640 uint32 per warp per parity
#define XE_OFF    86016
#define XO_OFF    (XE_OFF + NWARP * XBUF_W * 4)   // 126976
#define SLC_OFF   (XO_OFF + NWARP * XBUF_W * 4)   // 167936
#define SLW_OFF   (SLC_OFF + 256)
#define SGRP_OFF  (SLW_OFF + 256)
#define SMEM_TOTAL (SGRP_OFF + 512)

__device__ uint32_t g_Bfrag[SB_WORDS];
__device__ float  g_lc[K];
__device__ float  g_lwv[K];
__device__ double g_acc;
__device__ int    g_counter;
__device__ int    g_counter2;
__device__ int    g_done;
__device__ int    g_prep_done;

__device__ __forceinline__ void gdecode(int g, int& e, int& d, bool& lin) {
    if (g >= 80) { lin = true; e = (g - 80) * 8; d = 0; return; }
    lin = false;
    if (g < 32)      { d = g >> 2;            e = (g & 3) * 8; }
    else if (g < 56) { d = 8 + (g - 32) / 3;  e = ((g - 32) % 3) * 8; }
    else if (g < 72) { d = 16 + ((g - 56) >> 1); e = ((g - 56) & 1) * 8; }
    else             { d = 24 + (g - 72);     e = 0; }
}

__device__ __forceinline__ uint32_t hmul2u(uint32_t a, uint32_t b) {
    __half2 r = __hmul2(*(__half2*)&a, *(__half2*)&b);
    return *(uint32_t*)&r;
}

__device__ __forceinline__ void mmaf16(float* c, uint32_t a0, uint32_t a1,
                                       uint32_t a2, uint32_t a3,
                                       uint32_t b0, uint32_t b1) {
    asm volatile(
        "mma.sync.aligned.m16n8k16.row.col.f32.f16.f16.f32 "
        "{%0,%1,%2,%3}, {%4,%5,%6,%7}, {%8,%9}, {%0,%1,%2,%3};"
        : "+f"(c[0]), "+f"(c[1]), "+f"(c[2]), "+f"(c[3])
        : "r"(a0), "r"(a1), "r"(a2), "r"(a3), "r"(b0), "r"(b1));
}

// ---------------------------------------------------------------------------
// Prep body (R15, validated): entered by ALL TPB threads of CTAs 0..63.
// ---------------------------------------------------------------------------
__device__ void prep_body(char* smem, int k, int tid,
                          const float* __restrict__ means,
                          const float* __restrict__ scale_tril,
                          const float* __restrict__ log_weights) {
    float (*Ls)[D]     = (float(*)[D])(smem);
    float (*As)[D + 1] = (float(*)[D + 1])(smem + 4096);
    float* mu = (float*)(smem + 8448);
    float* u  = (float*)(smem + 8448 + 128);
    float* b  = (float*)(smem + 8448 + 256);
    float* rv = (float*)(smem + 8448 + 384);

    for (int i = tid; i < D * D; i += TPB)
        Ls[i / D][i % D] = scale_tril[k * D * D + i];
    __syncthreads();

    float hld = 0.0f, c = 0.0f, lse = 0.0f;
    if (tid < 32) {
        int t = tid;
        mu[t] = means[k * D + t];
        rv[t] = 1.0f / Ls[t][t];
        __syncwarp();

        hld = logf(Ls[t][t]);
        #pragma unroll
        for (int o = 16; o; o >>= 1) hld += __shfl_xor_sync(~0u, hld, o);

        {
            float s[D];
            #pragma unroll
            for (int i = 0; i < D; i++) s[i] = 0.0f;
            #pragma unroll
            for (int j = 0; j < D; j++) {
                float del = (j == t) ? 1.0f : 0.0f;
                float aj = (del - s[j]) * rv[j];
                As[j][t] = aj;
                #pragma unroll
                for (int i = j + 1; i < D; i++)
                    s[i] = fmaf(Ls[i][j], aj, s[i]);
            }
        }
        __syncwarp();

        { float s = 0.0f; for (int j = 0; j <= t; j++) s += As[t][j] * mu[j]; u[t] = s; }
        __syncwarp();
        { float s = 0.0f; for (int r = t; r < D; r++) s += As[r][t] * u[r]; b[t] = s; }
        __syncwarp();
        c = b[t] * mu[t];
        #pragma unroll
        for (int o = 16; o; o >>= 1) c += __shfl_xor_sync(~0u, c, o);

        float v0 = log_weights[t], v1 = log_weights[t + 32];
        float mx = fmaxf(v0, v1);
        #pragma unroll
        for (int o = 16; o; o >>= 1) mx = fmaxf(mx, __shfl_xor_sync(~0u, mx, o));
        float se = expf(v0 - mx) + expf(v1 - mx);
        #pragma unroll
        for (int o = 16; o; o >>= 1) se += __shfl_xor_sync(~0u, se, o);
        lse = mx + logf(se);
    }
    __syncthreads();

    __half* Bh = (__half*)g_Bfrag;
    for (int idx = tid; idx < NG * 8; idx += TPB) {
        int g = idx >> 3, cc = idx & 7;
        int e, d; bool lin;
        gdecode(g, e, d, lin);
        float v;
        if (lin) {
            v = -2.0f * b[e + cc];
        } else {
            int i = e + cc, j = i + d;
            if (j > 31) v = 0.0f;
            else {
                float s = 0.0f;
                for (int r = j; r < D; r++) s += As[r][i] * As[r][j];
                v = (d == 0) ? s : 2.0f * s;
            }
        }
        int kk = (g & 1) * 8 + cc, s_ = g >> 1;
        int rr = kk >> 3, kkl = kk & 7, tt = kkl >> 1, hh = kkl & 1;
        int nt = k >> 3, q = nt >> 1, w = (nt & 1) * 2 + rr;
        int L = (k & 7) * 4 + tt;
        Bh[((((s_ * 4 + q) * 32 + L) * 4) + w) * 2 + hh] = __float2half(v);
    }

    if (tid == 0) {
        float lwk = log_weights[k] - lse;
        g_lwv[k] = lwk;
        g_lc[k]  = -0.5f * (c + (float)D * LOG_2PI) - hld + lwk;
    }
    __syncthreads();
    if (tid == 0) {
        __threadfence();
        atomicAdd(&g_prep_done, 1);
    }
}

// ---------------------------------------------------------------------------
// One work unit of M*16 samples starting at `base` (M = 2 full, 1 half).
// Returns this thread's partial sum of resp-weighted logp.
// ---------------------------------------------------------------------------
template <int M>
__device__ __forceinline__ float do_unit(
        int base, int N, const float* __restrict__ X,
        uint32_t* xe, uint32_t* xo, const uint4* sB4,
        const float* sLC, const float* sLW, const uint32_t* sGrp,
        int lane, int gq, int t) {
    // stage x: rows 0..(16M-1), lane handles row = lane (lane < 16M)
    __syncwarp();
    if (lane < 16 * M) {
        int row = lane;
        int n = base + row;
        float xv[33];
        if (n < N) {
            const float4* xp = (const float4*)X + (size_t)n * 8;
            #pragma unroll
            for (int v = 0; v < 8; v++) {
                float4 f4 = xp[v];
                xv[4*v] = f4.x; xv[4*v+1] = f4.y;
                xv[4*v+2] = f4.z; xv[4*v+3] = f4.w;
            }
        } else {
            #pragma unroll
            for (int i = 0; i < D; i++) xv[i] = 0.0f;
        }
        xv[32] = 0.0f;
        uint32_t* xer = xe + row * 20;
        uint32_t* xor_ = xo + row * 20;
        #pragma unroll
        for (int p = 0; p < 16; p++) {
            __half2 h = __floats2half2_rn(xv[2*p], xv[2*p+1]);
            xer[p] = *(uint32_t*)&h;
            __half2 ho = __floats2half2_rn(xv[2*p+1], xv[2*p+2]);
            xor_[p] = *(uint32_t*)&ho;
        }
        #pragma unroll
        for (int p = 16; p < 20; p++) { xer[p] = 0u; xor_[p] = 0u; }
    }
    __syncwarp();

    const int rb0 = gq * 20 + t;
    const int rb1 = (gq + 8) * 20 + t;
    const int rb2 = (gq + 16) * 20 + t;
    const int rb3 = (gq + 24) * 20 + t;

    float acc[M][8][4];
    #pragma unroll
    for (int m = 0; m < M; m++)
        #pragma unroll
        for (int nt = 0; nt < 8; nt++)
            #pragma unroll
            for (int r = 0; r < 4; r++) acc[m][nt][r] = 0.0f;

    uint32_t mE = sGrp[0], mO = sGrp[1];
    for (int s = 0; s < NKS; s++) {
        const uint32_t gE = mE, gO = mO;
        mE = sGrp[2 * s + 2];
        mO = sGrp[2 * s + 3];

        const int p1E = gE & 0xff, p2E = (gE >> 8) & 0xff;
        const int p1O = gO & 0xff, p2O = (gO >> 8) & 0xff;
        const uint32_t* x2E = ((gE >> 16) & 1) ? xo : xe;
        const uint32_t* x2O = ((gO >> 16) & 1) ? xo : xe;
        const bool linE = (gE >> 17) & 1, linO = (gO >> 17) & 1;

        uint32_t a0[M], a1[M], a2[M], a3[M];
        {
            uint32_t e1a = xe[rb0 + p1E], e2a = x2E[rb0 + p2E];
            uint32_t e1b = xe[rb1 + p1E], e2b = x2E[rb1 + p2E];
            uint32_t e1c = xe[rb0 + p1O], e2c = x2O[rb0 + p2O];
            uint32_t e1d = xe[rb1 + p1O], e2d = x2O[rb1 + p2O];
            a0[0] = linE ? e1a : hmul2u(e1a, e2a);
            a1[0] = linE ? e1b : hmul2u(e1b, e2b);
            a2[0] = linO ? e1c : hmul2u(e1c, e2c);
            a3[0] = linO ? e1d : hmul2u(e1d, e2d);
        }
        if (M == 2) {
            uint32_t f1a = xe[rb2 + p1E], f2a = x2E[rb2 + p2E];
            uint32_t f1b = xe[rb3 + p1E], f2b = x2E[rb3 + p2E];
            uint32_t f1c = xe[rb2 + p1O], f2c = x2O[rb2 + p2O];
            uint32_t f1d = xe[rb3 + p1O], f2d = x2O[rb3 + p2O];
            a0[M-1] = linE ? f1a : hmul2u(f1a, f2a);
            a1[M-1] = linE ? f1b : hmul2u(f1b, f2b);
            a2[M-1] = linO ? f1c : hmul2u(f1c, f2c);
            a3[M-1] = linO ? f1d : hmul2u(f1d, f2d);
        }

        #pragma unroll
        for (int q = 0; q < 4; q++) {
            uint4 B = sB4[(s * 4 + q) * 32 + lane];
            #pragma unroll
            for (int m = 0; m < M; m++) {
                mmaf16(acc[m][2*q],   a0[m], a1[m], a2[m], a3[m], B.x, B.y);
                mmaf16(acc[m][2*q+1], a0[m], a1[m], a2[m], a3[m], B.z, B.w);
            }
        }
    }

    float accf = 0.0f;
    #pragma unroll
    for (int m = 0; m < M; m++) {
        #pragma unroll
        for (int rh = 0; rh < 2; rh++) {
            int n = base + gq + 16 * m + 8 * rh;
            float glp[16], mx = -1e30f;
            #pragma unroll
            for (int nt = 0; nt < 8; nt++) {
                #pragma unroll
                for (int h = 0; h < 2; h++) {
                    int col = nt * 8 + 2 * t + h;
                    float g = fmaf(-0.5f, acc[m][nt][rh * 2 + h], sLC[col]);
                    glp[nt * 2 + h] = g;
                    mx = fmaxf(mx, g);
                }
            }
            mx = fmaxf(mx, __shfl_xor_sync(~0u, mx, 1));
            mx = fmaxf(mx, __shfl_xor_sync(~0u, mx, 2));
            float S = 0.0f, T = 0.0f;
            #pragma unroll
            for (int nt = 0; nt < 8; nt++) {
                #pragma unroll
                for (int h = 0; h < 2; h++) {
                    int col = nt * 8 + 2 * t + h;
                    float e = __expf(glp[nt * 2 + h] - mx);
                    S += e;
                    T = fmaf(e, glp[nt * 2 + h] - sLW[col], T);
                }
            }
            S += __shfl_xor_sync(~0u, S, 1);
            S += __shfl_xor_sync(~0u, S, 2);
            T += __shfl_xor_sync(~0u, T, 1);
            T += __shfl_xor_sync(~0u, T, 2);
            if (t == 0 && n < N) accf += T / S;
        }
    }
    return accf;
}

// ---------------------------------------------------------------------------
// Fused kernel: prep -> spin -> phase A (full units) -> phase B (half units).
// ---------------------------------------------------------------------------
__global__ void __launch_bounds__(TPB, 1) gmm_fused(
        const float* __restrict__ X,
        const float* __restrict__ means,
        const float* __restrict__ scale_tril,
        const float* __restrict__ log_weights,
        float* __restrict__ out, int N, int nunits) {
    extern __shared__ char smem[];
    const int tid = threadIdx.x;
    const int wid = tid >> 5;
    const int lane = tid & 31;
    const int gq = lane >> 2;
    const int t  = lane & 3;

    if (blockIdx.x < 64)
        prep_body(smem, blockIdx.x, tid, means, scale_tril, log_weights);

    if (tid == 0) {
        while (atomicAdd(&g_prep_done, 0) < 64) { }
    }
    __syncthreads();

    float* sLC = (float*)(smem + SLC_OFF);
    float* sLW = (float*)(smem + SLW_OFF);
    uint32_t* sGrp = (uint32_t*)(smem + SGRP_OFF);
    const uint4* sB4 = (const uint4*)(smem + SB_OFF);

    for (int i = tid; i < SB_WORDS; i += TPB)
        ((uint32_t*)(smem + SB_OFF))[i] = g_Bfrag[i];
    if (tid < K) { sLC[tid] = g_lc[tid]; sLW[tid] = g_lwv[tid]; }
    if (tid < NG) {
        int e, d; bool lin;
        gdecode(tid, e, d, lin);
        int j2 = e + d;
        sGrp[tid] = (uint32_t)(e >> 1) | ((uint32_t)(j2 >> 1) << 8)
                  | ((uint32_t)(j2 & 1) << 16) | (lin ? (1u << 17) : 0u);
    }
    if (tid >= NG && tid < NG + 2) sGrp[tid] = 0u;
    __syncthreads();

    uint32_t* xe = (uint32_t*)(smem + XE_OFF) + wid * XBUF_W;
    uint32_t* xo = (uint32_t*)(smem + XO_OFF) + wid * XBUF_W;

    const int twarps = (int)gridDim.x * NWARP;
    const int split = (nunits < twarps) ? nunits : twarps;   // phase-A units
    const int htail = 2 * (nunits - split);                  // half units

    float accf = 0.0f;

    // phase A: full 32-sample units
    for (;;) {
        int u;
        if (lane == 0) u = atomicAdd(&g_counter, 1);
        u = __shfl_sync(~0u, u, 0);
        if (u >= split) break;
        accf += do_unit<2>(u * UNIT, N, X, xe, xo, sB4, sLC, sLW, sGrp,
                           lane, gq, t);
    }
    // phase B: 16-sample half units over the remainder
    for (;;) {
        int h;
        if (lane == 0) h = atomicAdd(&g_counter2, 1);
        h = __shfl_sync(~0u, h, 0);
        if (h >= htail) break;
        accf += do_unit<1>(split * UNIT + h * 16, N, X, xe, xo, sB4, sLC, sLW,
                           sGrp, lane, gq, t);
    }

    #pragma unroll
    for (int o = 16; o; o >>= 1) accf += __shfl_xor_sync(~0u, accf, o);
    if (lane == 0) atomicAdd(&g_acc, (double)accf);

    __syncthreads();
    __threadfence();
    if (tid == 0) {
        if (atomicAdd(&g_done, 1) == (int)gridDim.x - 1) {
            double total = atomicAdd(&g_acc, 0.0);
            out[0] = (float)(-total / (double)N);
            g_acc = 0.0;
            g_counter = 0;
            g_counter2 = 0;
            g_prep_done = 0;
            g_done = 0;
            __threadfence();
        }
    }
}

// ---------------------------------------------------------------------------
extern "C" void kernel_launch(void* const* d_in, const int* in_sizes, int n_in,
                              void* d_out, int out_size) {
    const float* X           = (const float*)d_in[0];
    const float* means       = (const float*)d_in[1];
    const float* scale_tril  = (const float*)d_in[2];
    const float* log_weights = (const float*)d_in[3];
    float* out = (float*)d_out;

    int N = in_sizes[0] / D;
    int nunits = (N + UNIT - 1) / UNIT;

    cudaFuncSetAttribute(gmm_fused, cudaFuncAttributeMaxDynamicSharedMemorySize,
                         SMEM_TOTAL);
    int nsm = 148;
    cudaDeviceGetAttribute(&nsm, cudaDevAttrMultiProcessorCount, 0);

    gmm_fused<<<nsm, TPB, SMEM_TOTAL>>>(X, means, scale_tril, log_weights,
                                        out, N, nunits);
}

// round 17
// speedup vs baseline: 1.0907x; 1.0907x over previous
#include <cuda_runtime.h>
#include <cuda_fp16.h>
#include <math.h>
#include <stdint.h>

// GMM_64003602645506 — warp-independent fp16 mma.sync GEMM, barrier-free.
// R17: R15 fused kernel + e-blocked feature ordering: groups sorted by e so
// the first operand is block-constant (preloaded register) — per-kstep A
// loads drop 16 -> 8 LDS. 88 groups (padded), NKS=44, single steal phase.

#define D        32
#define K        64
#define NG2      88
#define NKS      44
#define UNIT     32
#define TPB      512
#define NWARP    16
#define LOG_2PI  1.8378770664093453f

// smem layout (bytes)
#define SB_WORDS  (NKS * 4 * 32 * 4)          // 22528 uint32 (90112 B)
#define SB_OFF    0
#define XBUF_W    (UNIT * 20)                 // 640 uint32 per warp per parity
#define XE_OFF    90112
#define XO_OFF    (XE_OFF + NWARP * XBUF_W * 4)   // 131072
#define SLC_OFF   (XO_OFF + NWARP * XBUF_W * 4)   // 172032
#define SLW_OFF   (SLC_OFF + 256)
#define SGRP_OFF  (SLW_OFF + 256)
#define SMEM_TOTAL (SGRP_OFF + 512)

__device__ uint32_t g_Bfrag[SB_WORDS];
__device__ float  g_lc[K];
__device__ float  g_lwv[K];
__device__ double g_acc;
__device__ int    g_counter;
__device__ int    g_done;
__device__ int    g_prep_done;

// e-blocked group order: e=0 (d=0..31, lin, pad) | e=8 (d=0..23, lin, pad)
// | e=16 (d=0..15, lin, pad) | e=24 (d=0..7, lin, pad)  -> 34+26+18+10 = 88
__device__ __forceinline__ void gdecode2(int g, int& e, int& d,
                                         bool& lin, bool& pad) {
    int idx, qc;
    if (g < 34)      { e = 0;  idx = g;      qc = 32; }
    else if (g < 60) { e = 8;  idx = g - 34; qc = 24; }
    else if (g < 78) { e = 16; idx = g - 60; qc = 16; }
    else             { e = 24; idx = g - 78; qc = 8;  }
    lin = false; pad = false; d = 0;
    if (idx < qc)       d = idx;
    else if (idx == qc) lin = true;
    else                pad = true;
}

__device__ __forceinline__ uint32_t hmul2u(uint32_t a, uint32_t b) {
    __half2 r = __hmul2(*(__half2*)&a, *(__half2*)&b);
    return *(uint32_t*)&r;
}

__device__ __forceinline__ void mmaf16(float* c, uint32_t a0, uint32_t a1,
                                       uint32_t a2, uint32_t a3,
                                       uint32_t b0, uint32_t b1) {
    asm volatile(
        "mma.sync.aligned.m16n8k16.row.col.f32.f16.f16.f32 "
        "{%0,%1,%2,%3}, {%4,%5,%6,%7}, {%8,%9}, {%0,%1,%2,%3};"
        : "+f"(c[0]), "+f"(c[1]), "+f"(c[2]), "+f"(c[3])
        : "r"(a0), "r"(a1), "r"(a2), "r"(a3), "r"(b0), "r"(b1));
}

// ---------------------------------------------------------------------------
// Prep body: entered by ALL TPB threads of CTAs 0..63 (k = blockIdx.x).
// Emits B fragments in the NEW e-blocked group order.
// ---------------------------------------------------------------------------
__device__ void prep_body(char* smem, int k, int tid,
                          const float* __restrict__ means,
                          const float* __restrict__ scale_tril,
                          const float* __restrict__ log_weights) {
    float (*Ls)[D]     = (float(*)[D])(smem);
    float (*As)[D + 1] = (float(*)[D + 1])(smem + 4096);
    float* mu = (float*)(smem + 8448);
    float* u  = (float*)(smem + 8448 + 128);
    float* b  = (float*)(smem + 8448 + 256);
    float* rv = (float*)(smem + 8448 + 384);

    for (int i = tid; i < D * D; i += TPB)
        Ls[i / D][i % D] = scale_tril[k * D * D + i];
    __syncthreads();

    float hld = 0.0f, c = 0.0f, lse = 0.0f;
    if (tid < 32) {
        int t = tid;
        mu[t] = means[k * D + t];
        rv[t] = 1.0f / Ls[t][t];
        __syncwarp();

        hld = logf(Ls[t][t]);
        #pragma unroll
        for (int o = 16; o; o >>= 1) hld += __shfl_xor_sync(~0u, hld, o);

        {
            float s[D];
            #pragma unroll
            for (int i = 0; i < D; i++) s[i] = 0.0f;
            #pragma unroll
            for (int j = 0; j < D; j++) {
                float del = (j == t) ? 1.0f : 0.0f;
                float aj = (del - s[j]) * rv[j];
                As[j][t] = aj;
                #pragma unroll
                for (int i = j + 1; i < D; i++)
                    s[i] = fmaf(Ls[i][j], aj, s[i]);
            }
        }
        __syncwarp();

        { float s = 0.0f; for (int j = 0; j <= t; j++) s += As[t][j] * mu[j]; u[t] = s; }
        __syncwarp();
        { float s = 0.0f; for (int r = t; r < D; r++) s += As[r][t] * u[r]; b[t] = s; }
        __syncwarp();
        c = b[t] * mu[t];
        #pragma unroll
        for (int o = 16; o; o >>= 1) c += __shfl_xor_sync(~0u, c, o);

        float v0 = log_weights[t], v1 = log_weights[t + 32];
        float mx = fmaxf(v0, v1);
        #pragma unroll
        for (int o = 16; o; o >>= 1) mx = fmaxf(mx, __shfl_xor_sync(~0u, mx, o));
        float se = expf(v0 - mx) + expf(v1 - mx);
        #pragma unroll
        for (int o = 16; o; o >>= 1) se += __shfl_xor_sync(~0u, se, o);
        lse = mx + logf(se);
    }
    __syncthreads();

    __half* Bh = (__half*)g_Bfrag;
    for (int idx = tid; idx < NG2 * 8; idx += TPB) {
        int g = idx >> 3, cc = idx & 7;
        int e, d; bool lin, pad;
        gdecode2(g, e, d, lin, pad);
        float v = 0.0f;
        if (!pad) {
            if (lin) {
                v = -2.0f * b[e + cc];
            } else {
                int i = e + cc, j = i + d;
                if (j <= 31) {
                    float s = 0.0f;
                    for (int r = j; r < D; r++) s += As[r][i] * As[r][j];
                    v = (d == 0) ? s : 2.0f * s;
                }
            }
        }
        int kk = (g & 1) * 8 + cc, s_ = g >> 1;
        int rr = kk >> 3, kkl = kk & 7, tt = kkl >> 1, hh = kkl & 1;
        int nt = k >> 3, q = nt >> 1, w = (nt & 1) * 2 + rr;
        int L = (k & 7) * 4 + tt;
        Bh[((((s_ * 4 + q) * 32 + L) * 4) + w) * 2 + hh] = __float2half(v);
    }

    if (tid == 0) {
        float lwk = log_weights[k] - lse;
        g_lwv[k] = lwk;
        g_lc[k]  = -0.5f * (c + (float)D * LOG_2PI) - hld + lwk;
    }
    __syncthreads();
    if (tid == 0) {
        __threadfence();
        atomicAdd(&g_prep_done, 1);
    }
}

// ---------------------------------------------------------------------------
// Fused kernel: prep (CTAs 0..63) -> co-resident spin -> persistent GEMM.
// ---------------------------------------------------------------------------
__global__ void __launch_bounds__(TPB, 1) gmm_fused(
        const float* __restrict__ X,
        const float* __restrict__ means,
        const float* __restrict__ scale_tril,
        const float* __restrict__ log_weights,
        float* __restrict__ out, int N, int nunits) {
    extern __shared__ char smem[];
    const int tid = threadIdx.x;
    const int wid = tid >> 5;
    const int lane = tid & 31;
    const int gq = lane >> 2;
    const int t  = lane & 3;

    if (blockIdx.x < 64)
        prep_body(smem, blockIdx.x, tid, means, scale_tril, log_weights);

    if (tid == 0) {
        while (atomicAdd(&g_prep_done, 0) < 64) { }
    }
    __syncthreads();

    float* sLC = (float*)(smem + SLC_OFF);
    float* sLW = (float*)(smem + SLW_OFF);
    uint32_t* sGrp = (uint32_t*)(smem + SGRP_OFF);
    const uint4* sB4 = (const uint4*)(smem + SB_OFF);

    for (int i = tid; i < SB_WORDS; i += TPB)
        ((uint32_t*)(smem + SB_OFF))[i] = g_Bfrag[i];
    if (tid < K) { sLC[tid] = g_lc[tid]; sLW[tid] = g_lwv[tid]; }
    if (tid < NG2) {
        int e, d; bool lin, pad;
        gdecode2(tid, e, d, lin, pad);
        uint32_t w;
        if (pad)      w = 16u;                 // quad vs zero pad words
        else if (lin) w = (1u << 17);
        else {
            int j2 = e + d;
            w = (uint32_t)(j2 >> 1) | ((uint32_t)(j2 & 1) << 16);
        }
        sGrp[tid] = w;
    }
    __syncthreads();

    uint32_t* xe = (uint32_t*)(smem + XE_OFF) + wid * XBUF_W;
    uint32_t* xo = (uint32_t*)(smem + XO_OFF) + wid * XBUF_W;

    const int rb0 = gq * 20 + t;
    const int rb1 = (gq + 8) * 20 + t;
    const int rb2 = (gq + 16) * 20 + t;
    const int rb3 = (gq + 24) * 20 + t;

    float accf = 0.0f;

    for (;;) {
        int u;
        if (lane == 0) u = atomicAdd(&g_counter, 1);
        u = __shfl_sync(~0u, u, 0);
        if (u >= nunits) break;
        const int base = u * UNIT;

        __syncwarp();
        {
            int row = lane;
            int n = base + row;
            float xv[33];
            if (n < N) {
                const float4* xp = (const float4*)X + (size_t)n * 8;
                #pragma unroll
                for (int v = 0; v < 8; v++) {
                    float4 f4 = xp[v];
                    xv[4*v] = f4.x; xv[4*v+1] = f4.y;
                    xv[4*v+2] = f4.z; xv[4*v+3] = f4.w;
                }
            } else {
                #pragma unroll
                for (int i = 0; i < D; i++) xv[i] = 0.0f;
            }
            xv[32] = 0.0f;
            uint32_t* xer = xe + row * 20;
            uint32_t* xor_ = xo + row * 20;
            #pragma unroll
            for (int p = 0; p < 16; p++) {
                __half2 h = __floats2half2_rn(xv[2*p], xv[2*p+1]);
                xer[p] = *(uint32_t*)&h;
                __half2 ho = __floats2half2_rn(xv[2*p+1], xv[2*p+2]);
                xor_[p] = *(uint32_t*)&ho;
            }
            #pragma unroll
            for (int p = 16; p < 20; p++) { xer[p] = 0u; xor_[p] = 0u; }
        }
        __syncwarp();

        float acc[2][8][4];
        #pragma unroll
        for (int m = 0; m < 2; m++)
            #pragma unroll
            for (int nt = 0; nt < 8; nt++)
                #pragma unroll
                for (int r = 0; r < 4; r++) acc[m][nt][r] = 0.0f;

        // e-blocked mainloop: first operand preloaded per block
        int s = 0;
        #pragma unroll
        for (int eb = 0; eb < 4; eb++) {
            const int EP = eb * 4;                       // e>>1
            const int KB = (eb == 0) ? 17 : (eb == 1) ? 13 : (eb == 2) ? 9 : 5;
            const uint32_t e10 = xe[rb0 + EP];
            const uint32_t e11 = xe[rb1 + EP];
            const uint32_t e12 = xe[rb2 + EP];
            const uint32_t e13 = xe[rb3 + EP];
            #pragma unroll 1
            for (int sl = 0; sl < KB; sl++, s++) {
                uint2 gg = ((const uint2*)sGrp)[s];
                const uint32_t gE = gg.x, gO = gg.y;
                const int p2E = gE & 0xff, p2O = gO & 0xff;
                const uint32_t* x2E = ((gE >> 16) & 1) ? xo : xe;
                const uint32_t* x2O = ((gO >> 16) & 1) ? xo : xe;
                const bool linE = (gE >> 17) & 1, linO = (gO >> 17) & 1;

                uint32_t sE0 = x2E[rb0 + p2E], sE1 = x2E[rb1 + p2E];
                uint32_t sE2 = x2E[rb2 + p2E], sE3 = x2E[rb3 + p2E];
                uint32_t sO0 = x2O[rb0 + p2O], sO1 = x2O[rb1 + p2O];
                uint32_t sO2 = x2O[rb2 + p2O], sO3 = x2O[rb3 + p2O];

                uint32_t a00 = linE ? e10 : hmul2u(e10, sE0);
                uint32_t a10 = linE ? e11 : hmul2u(e11, sE1);
                uint32_t a20 = linO ? e10 : hmul2u(e10, sO0);
                uint32_t a30 = linO ? e11 : hmul2u(e11, sO1);
                uint32_t a01 = linE ? e12 : hmul2u(e12, sE2);
                uint32_t a11 = linE ? e13 : hmul2u(e13, sE3);
                uint32_t a21 = linO ? e12 : hmul2u(e12, sO2);
                uint32_t a31 = linO ? e13 : hmul2u(e13, sO3);

                #pragma unroll
                for (int q = 0; q < 4; q++) {
                    uint4 B = sB4[(s * 4 + q) * 32 + lane];
                    mmaf16(acc[0][2*q],   a00, a10, a20, a30, B.x, B.y);
                    mmaf16(acc[0][2*q+1], a00, a10, a20, a30, B.z, B.w);
                    mmaf16(acc[1][2*q],   a01, a11, a21, a31, B.x, B.y);
                    mmaf16(acc[1][2*q+1], a01, a11, a21, a31, B.z, B.w);
                }
            }
        }

        // epilogue
        #pragma unroll
        for (int m = 0; m < 2; m++) {
            #pragma unroll
            for (int rh = 0; rh < 2; rh++) {
                int n = base + gq + 16 * m + 8 * rh;
                float glp[16], mx = -1e30f;
                #pragma unroll
                for (int nt = 0; nt < 8; nt++) {
                    #pragma unroll
                    for (int h = 0; h < 2; h++) {
                        int col = nt * 8 + 2 * t + h;
                        float g = fmaf(-0.5f, acc[m][nt][rh * 2 + h], sLC[col]);
                        glp[nt * 2 + h] = g;
                        mx = fmaxf(mx, g);
                    }
                }
                mx = fmaxf(mx, __shfl_xor_sync(~0u, mx, 1));
                mx = fmaxf(mx, __shfl_xor_sync(~0u, mx, 2));
                float S = 0.0f, T = 0.0f;
                #pragma unroll
                for (int nt = 0; nt < 8; nt++) {
                    #pragma unroll
                    for (int h = 0; h < 2; h++) {
                        int col = nt * 8 + 2 * t + h;
                        float e = __expf(glp[nt * 2 + h] - mx);
                        S += e;
                        T = fmaf(e, glp[nt * 2 + h] - sLW[col], T);
                    }
                }
                S += __shfl_xor_sync(~0u, S, 1);
                S += __shfl_xor_sync(~0u, S, 2);
                T += __shfl_xor_sync(~0u, T, 1);
                T += __shfl_xor_sync(~0u, T, 2);
                if (t == 0 && n < N) accf += T / S;
            }
        }
    }

    #pragma unroll
    for (int o = 16; o; o >>= 1) accf += __shfl_xor_sync(~0u, accf, o);
    if (lane == 0) atomicAdd(&g_acc, (double)accf);

    __syncthreads();
    __threadfence();
    if (tid == 0) {
        if (atomicAdd(&g_done, 1) == (int)gridDim.x - 1) {
            double total = atomicAdd(&g_acc, 0.0);
            out[0] = (float)(-total / (double)N);
            g_acc = 0.0;
            g_counter = 0;
            g_prep_done = 0;
            g_done = 0;
            __threadfence();
        }
    }
}

// ---------------------------------------------------------------------------
extern "C" void kernel_launch(void* const* d_in, const int* in_sizes, int n_in,
                              void* d_out, int out_size) {
    const float* X           = (const float*)d_in[0];
    const float* means       = (const float*)d_in[1];
    const float* scale_tril  = (const float*)d_in[2];
    const float* log_weights = (const float*)d_in[3];
    float* out = (float*)d_out;

    int N = in_sizes[0] / D;
    int nunits = (N + UNIT - 1) / UNIT;

    cudaFuncSetAttribute(gmm_fused, cudaFuncAttributeMaxDynamicSharedMemorySize,
                         SMEM_TOTAL);
    int nsm = 148;
    cudaDeviceGetAttribute(&nsm, cudaDevAttrMultiProcessorCount, 0);

    gmm_fused<<<nsm, TPB, SMEM_TOTAL>>>(X, means, scale_tril, log_weights,
                                        out, N, nunits);
}